// round 11
// baseline (speedup 1.0000x reference)
#include <cuda_runtime.h>
#include <cstdint>
#include <cstddef>

// Problem constants
#define NN 32768
#define KK 8192
#define DD 64

// Output layout (tuple order, flattened)
#define OFF_CB  268435456ULL
#define OFF_CS  268959744ULL
#define OFF_EMA 268967936ULL
#define OFF_EMB 269492224ULL

#define DECAY 0.99f
#define OMD   0.01f
#define EPSV  1e-5f
#define KEPS  0.08192f   // K * EPS

// Scratch (device globals; no allocations allowed)
__device__ int   g_idx[NN];
__device__ float g_e2[KK];
__device__ int   g_e2max_i;      // max ||e||^2 as ordered int (positive floats)
__device__ float g_cnt[KK];
__device__ float g_dw[KK * DD];
__device__ float g_n;

// ===========================================================================
// helpers (sm_80-era PTX only: safe for the plain sm_103 ptxas target)
// ===========================================================================
static __device__ __forceinline__ uint32_t smem_u32(const void* p) {
    uint32_t a;
    asm("{ .reg .u64 t; cvta.to.shared.u64 t, %1; cvt.u32.u64 %0, t; }"
        : "=r"(a) : "l"(p));
    return a;
}

#define CP_ASYNC16(dst, src) \
    asm volatile("cp.async.cg.shared.global [%0], [%1], 16;" \
                 :: "r"(dst), "l"(src) : "memory")
#define CP_COMMIT() asm volatile("cp.async.commit_group;" ::: "memory")
#define CP_WAIT0()  asm volatile("cp.async.wait_group 0;"  ::: "memory")

// m16n8k16 row.col bf16 MMA, D += A*B (C aliases D)
static __device__ __forceinline__ void mma_bf16(float* d, const uint32_t* a,
                                                const uint32_t* b) {
    asm volatile(
        "mma.sync.aligned.m16n8k16.row.col.f32.bf16.bf16.f32 "
        "{%0,%1,%2,%3}, {%4,%5,%6,%7}, {%8,%9}, {%0,%1,%2,%3};"
        : "+f"(d[0]), "+f"(d[1]), "+f"(d[2]), "+f"(d[3])
        : "r"(a[0]), "r"(a[1]), "r"(a[2]), "r"(a[3]), "r"(b[0]), "r"(b[1]));
}

// pack two f32 -> bf16x2 (lo = first element / even k, hi = odd k)
static __device__ __forceinline__ uint32_t pack_bf16(float lo, float hi) {
    uint32_t d;
    asm("cvt.rn.bf16x2.f32 %0, %1, %2;" : "=r"(d) : "f"(hi), "f"(lo));
    return d;
}

// ===========================================================================
// 0) zero scratch
// ===========================================================================
__global__ void zero_scratch_kernel() {
    int i = blockIdx.x * 256 + threadIdx.x;
    if (i < KK * DD) g_dw[i] = 0.0f;
    if (i < KK)      g_cnt[i] = 0.0f;
    if (i == 0)      g_e2max_i = 0;
}

// ===========================================================================
// 1) codebook squared norms + max norm
// ===========================================================================
__global__ void e2_kernel(const float* __restrict__ e) {
    int k = blockIdx.x * 256 + threadIdx.x;
    const float4* p = reinterpret_cast<const float4*>(e + (size_t)k * DD);
    float s = 0.0f;
#pragma unroll
    for (int i = 0; i < 16; ++i) {
        float4 v = p[i];
        s += v.x * v.x + v.y * v.y + v.z * v.z + v.w * v.w;
    }
    g_e2[k] = s;
    atomicMax(&g_e2max_i, __float_as_int(s));   // positive floats: int order ok
}

// ===========================================================================
// 2) Fused argmin (bf16 filter + exact fp32 rescue) + encodings + scatter.
//    CTA = 256 threads = 8 warps, 4(m) x 2(n); 128 rows per CTA, 2 CTAs/SM.
//    Approx distances via single-term bf16 m16n8k16 HMMA (A persistent in
//    32 regs).  Any candidate within a provable error margin of the running
//    minimum is rescored with an exact fp32 serial-FMA dot (same arithmetic
//    as the validated round-2 kernel); final selection uses exact values
//    only, so argmin decisions are exact.  One-hot zero stripe streams
//    inside the tile loop; 1.0-writes and dw/count scatter in the tail.
// ===========================================================================
#define RPC  128
#define SP   68                       // smem row stride in floats (64 + 4 pad)
#define SPB  (SP * 4)                 // 272 bytes
#define PLANE (128 * SPB)             // 34816 bytes
#define XRAW 0
#define EB0  PLANE
#define EB1  (2 * PLANE)
#define XS2  (3 * PLANE)                  // [128] float row norms^2
#define CAND_D (XS2 + 128 * 4)            // [2][128] float
#define CAND_I (CAND_D + 2 * 128 * 4)     // [2][128] int
#define WIN_OFF (CAND_I + 2 * 128 * 4)    // [128] int
#define ARG_SMEM (WIN_OFF + 128 * 4)      // 107520 bytes

// margin constant: 2 * (2 * 2.004 * 2^-8) * 1.34 safety pad
#define MARG_C 0.042f

__global__ __launch_bounds__(256, 2)
void argmin_mma_kernel(const float* __restrict__ x, const float* __restrict__ e,
                       float* __restrict__ out) {
    extern __shared__ char sm[];
    const uint32_t sb = smem_u32(sm);
    const int tid = threadIdx.x;
    const int wid = tid >> 5;
    const int lane = tid & 31;
    const int g = lane >> 2;          // group id (0..7)
    const int r = lane & 3;           // thread-in-group (0..3)
    const int mw = wid & 3;           // m-warp -> rows mw*32..+31
    const int nw = wid >> 2;          // n-warp -> cols nw*64..+63
    const int row0 = blockIdx.x * RPC;
    const int Cn = nw * 64;

    float* xs2    = reinterpret_cast<float*>(sm + XS2);
    float* cand_d = reinterpret_cast<float*>(sm + CAND_D);
    int*   cand_i = reinterpret_cast<int*>(sm + CAND_I);
    int*   win    = reinterpret_cast<int*>(sm + WIN_OFF);

    // ---- kick off e tile 0 prefetch (overlaps x staging) ----
    {
        const char* src = reinterpret_cast<const char*>(e);
#pragma unroll
        for (int i = 0; i < 8; ++i) {
            int ch = tid + 256 * i;
            int n = ch >> 4, kq = ch & 15;
            CP_ASYNC16(sb + EB0 + n * SPB + kq * 16, src + ch * 16);
        }
    }
    CP_COMMIT();

    // ---- stage raw x tile ----
    {
        const float4* xg = reinterpret_cast<const float4*>(x + (size_t)row0 * DD);
#pragma unroll
        for (int i = 0; i < 8; ++i) {
            int ch = tid + 256 * i;            // 0..2047 float4s
            int row = ch >> 4, q = ch & 15;
            *reinterpret_cast<float4*>(sm + XRAW + row * SPB + q * 16) = xg[ch];
        }
    }
    __syncthreads();

    // ---- row norms^2 ----
    if (tid < 128) {
        const float4* xr = reinterpret_cast<const float4*>(sm + XRAW + tid * SPB);
        float s = 0.0f;
#pragma unroll
        for (int i = 0; i < 16; ++i) {
            float4 v = xr[i];
            s += v.x * v.x + v.y * v.y + v.z * v.z + v.w * v.w;
        }
        xs2[tid] = s;
    }

    // ---- persistent bf16 A fragments: [mf][ks][4] ----
    uint32_t A[2][4][4];
#pragma unroll
    for (int mf = 0; mf < 2; ++mf)
#pragma unroll
        for (int ks = 0; ks < 4; ++ks)
#pragma unroll
            for (int j = 0; j < 4; ++j) {
                int row = mw * 32 + mf * 16 + g + ((j & 1) ? 8 : 0);
                int kb  = ks * 16 + ((j & 2) ? 8 : 0) + 2 * r;
                float2 v = *reinterpret_cast<const float2*>(
                    sm + XRAW + row * SPB + kb * 4);
                A[mf][ks][j] = pack_bf16(v.x, v.y);
            }

    CP_WAIT0();
    __syncthreads();

    // ---- per-slot state: rows mw*32 + g + s*8 ----
    const float emaxs = sqrtf(__int_as_float(g_e2max_i));
    float marg[4], cb[4], bex[4];
    int   bix[4];
#pragma unroll
    for (int s = 0; s < 4; ++s) {
        marg[s] = MARG_C * sqrtf(xs2[mw * 32 + g + s * 8]) * emaxs;
        cb[s]  = 3.402823466e38f;
        bex[s] = 3.402823466e38f;
        bix[s] = 0;
    }

    // encodings base (float4 granularity; row stride 2048 f4)
    float4* enc = reinterpret_cast<float4*>(out) + (size_t)row0 * 2048;
    const float4 fz = make_float4(0.0f, 0.0f, 0.0f, 0.0f);

    const int NTILES = KK / 128;   // 64
    for (int t = 0; t < NTILES; ++t) {
        const char* bufc = sm + (((t & 1) == 0) ? EB0 : EB1);

        // prefetch tile t+1
        if (t + 1 < NTILES) {
            const char* src = reinterpret_cast<const char*>(e + (size_t)(t + 1) * 128 * DD);
            const uint32_t bufn = sb + (((t & 1) == 0) ? EB1 : EB0);
#pragma unroll
            for (int i = 0; i < 8; ++i) {
                int ch = tid + 256 * i;
                int n = ch >> 4, kq = ch & 15;
                CP_ASYNC16(bufn + n * SPB + kq * 16, src + ch * 16);
            }
        }
        CP_COMMIT();

        // ---- zero stripe: rows [0,128) x f4-cols [t*32, t*32+32) ----
        {
            float4* zb = enc + t * 32;
#pragma unroll
            for (int j = 0; j < 16; ++j) {
                int i = tid + 256 * j;         // 0..4095
                int row = i >> 5, c4 = i & 31;
                __stcs(&zb[(size_t)row * 2048 + c4], fz);
            }
        }

        // rescue helper (exact fp32 serial-FMA dot, ascending d — identical
        // arithmetic to the validated round-2 kernel)
        auto process = [&](int s, int rowl, int colg, float e2v, float acc) {
            float dt = fmaf(-2.0f, acc, e2v);
            if (dt <= cb[s] + marg[s]) {
                const float4* xr = reinterpret_cast<const float4*>(
                    sm + XRAW + rowl * SPB);
                const float4* er = reinterpret_cast<const float4*>(
                    bufc + (size_t)(colg & 127) * SPB);
                float a2 = 0.0f;
#pragma unroll
                for (int i = 0; i < 16; ++i) {
                    float4 xv = xr[i], ev = er[i];
                    a2 = fmaf(xv.x, ev.x, a2);
                    a2 = fmaf(xv.y, ev.y, a2);
                    a2 = fmaf(xv.z, ev.z, a2);
                    a2 = fmaf(xv.w, ev.w, a2);
                }
                float ex = fmaf(-2.0f, a2, e2v);
                if (ex < bex[s]) { bex[s] = ex; bix[s] = colg; }  // ascending col
            }
            cb[s] = fminf(cb[s], dt);
        };

        // ---- compute in two n-halves (keeps D live regs at 32) ----
#pragma unroll
        for (int h = 0; h < 2; ++h) {
            float D[2][4][4];
#pragma unroll
            for (int mf = 0; mf < 2; ++mf)
#pragma unroll
                for (int nb = 0; nb < 4; ++nb)
#pragma unroll
                    for (int j = 0; j < 4; ++j) D[mf][nb][j] = 0.0f;

#pragma unroll
            for (int ks = 0; ks < 4; ++ks) {
                uint32_t B[4][2];
#pragma unroll
                for (int nb = 0; nb < 4; ++nb) {
                    const char* np = bufc +
                        (size_t)(Cn + h * 32 + nb * 8 + g) * SPB;
                    float2 p0 = *reinterpret_cast<const float2*>(
                        np + (ks * 16 + 2 * r) * 4);
                    float2 p1 = *reinterpret_cast<const float2*>(
                        np + (ks * 16 + 2 * r + 8) * 4);
                    B[nb][0] = pack_bf16(p0.x, p0.y);
                    B[nb][1] = pack_bf16(p1.x, p1.y);
                }
#pragma unroll
                for (int nb = 0; nb < 4; ++nb) {
                    mma_bf16(D[0][nb], A[0][ks], B[nb]);
                    mma_bf16(D[1][nb], A[1][ks], B[nb]);
                }
            }

            // epilogue for this half
#pragma unroll
            for (int nb = 0; nb < 4; ++nb) {
                int col = t * 128 + Cn + h * 32 + nb * 8 + r * 2;
                float2 q = *reinterpret_cast<const float2*>(&g_e2[col]);
#pragma unroll
                for (int mf = 0; mf < 2; ++mf) {
                    int rowl = mw * 32 + mf * 16 + g;
                    int s0 = mf * 2, s1 = mf * 2 + 1;
                    process(s0, rowl,     col,     q.x, D[mf][nb][0]);
                    process(s0, rowl,     col + 1, q.y, D[mf][nb][1]);
                    process(s1, rowl + 8, col,     q.x, D[mf][nb][2]);
                    process(s1, rowl + 8, col + 1, q.y, D[mf][nb][3]);
                }
            }
        }

        CP_WAIT0();
        __syncthreads();
    }

    // ---- reduce exact results across the 4 lanes of each quad ----
#pragma unroll
    for (int m = 1; m <= 2; m <<= 1) {
#pragma unroll
        for (int s = 0; s < 4; ++s) {
            float ob = __shfl_xor_sync(0xffffffffu, bex[s], m);
            int   oi = __shfl_xor_sync(0xffffffffu, bix[s], m);
            if (ob < bex[s] || (ob == bex[s] && oi < bix[s])) {
                bex[s] = ob; bix[s] = oi;
            }
        }
    }
    if (r == 0) {
#pragma unroll
        for (int s = 0; s < 4; ++s) {
            int row = mw * 32 + g + s * 8;
            cand_d[nw * 128 + row] = bex[s];
            cand_i[nw * 128 + row] = bix[s];
        }
    }
    __syncthreads();   // also orders zero stores before the 1.0 stores
    if (tid < 128) {
        float d0 = cand_d[tid], d1 = cand_d[128 + tid];
        int   i0 = cand_i[tid], i1 = cand_i[128 + tid];
        int bi = (d1 < d0 || (d1 == d0 && i1 < i0)) ? i1 : i0;
        win[tid] = bi;
        g_idx[row0 + tid] = bi;
        out[(size_t)(row0 + tid) * KK + bi] = 1.0f;   // the one-hot 1
    }
    __syncthreads();

    // ---- fused dw/count scatter for this CTA's 128 rows (x from smem) ----
    for (int i = tid; i < RPC * DD; i += 256) {
        int n = i >> 6, d = i & 63;
        int k = win[n];
        float xv = *reinterpret_cast<const float*>(sm + XRAW + n * SPB + d * 4);
        atomicAdd(&g_dw[(size_t)k * DD + d], xv);
        if (d == 0) atomicAdd(&g_cnt[k], 1.0f);
    }
}

// ===========================================================================
// 3) n = sum(cluster_size_pre)
// ===========================================================================
__global__ void reduce_n_kernel(const float* __restrict__ ema_cs) {
    __shared__ float sh[1024];
    int t = threadIdx.x;
    float s = 0.0f;
    for (int k = t; k < KK; k += 1024) {
        float cs = __fadd_rn(__fmul_rn(ema_cs[k], DECAY), __fmul_rn(OMD, g_cnt[k]));
        s += cs;
    }
    sh[t] = s;
    __syncthreads();
    for (int m = 512; m > 0; m >>= 1) {
        if (t < m) sh[t] += sh[t + m];
        __syncthreads();
    }
    if (t == 0) g_n = sh[0];
}

// ===========================================================================
// 4) finalize
// ===========================================================================
__global__ void finalize_kernel(const float* __restrict__ emb_w,
                                const float* __restrict__ ema_w,
                                const float* __restrict__ ema_cs,
                                float* __restrict__ out) {
    int gid = blockIdx.x * 256 + threadIdx.x;
    int k = gid >> 6, d = gid & 63;
    float nsum = g_n;
    float cs  = __fadd_rn(__fmul_rn(ema_cs[k], DECAY), __fmul_rn(OMD, g_cnt[k]));
    float csn = __fmul_rn(__fdiv_rn(__fadd_rn(cs, EPSV), __fadd_rn(nsum, KEPS)), nsum);
    float ema_new = __fadd_rn(__fmul_rn(ema_w[gid], DECAY), __fmul_rn(OMD, g_dw[gid]));
    out[OFF_CB  + gid] = emb_w[gid];
    out[OFF_EMA + gid] = ema_new;
    out[OFF_EMB + gid] = __fdiv_rn(ema_new, csn);
    if (d == 0) out[OFF_CS + k] = csn;
}

// ===========================================================================
extern "C" void kernel_launch(void* const* d_in, const int* in_sizes, int n_in,
                              void* d_out, int out_size) {
    const float* x       = (const float*)d_in[0];
    const float* emb_w   = (const float*)d_in[1];
    const float* ema_w   = (const float*)d_in[2];
    const float* ema_cs  = (const float*)d_in[3];
    float* out = (float*)d_out;

    cudaFuncSetAttribute(argmin_mma_kernel,
                         cudaFuncAttributeMaxDynamicSharedMemorySize, ARG_SMEM);

    zero_scratch_kernel<<<2048, 256>>>();
    e2_kernel<<<KK / 256, 256>>>(emb_w);
    argmin_mma_kernel<<<NN / RPC, 256, ARG_SMEM>>>(x, emb_w, out);
    reduce_n_kernel<<<1, 1024>>>(ema_cs);
    finalize_kernel<<<(KK * DD) / 256, 256>>>(emb_w, ema_w, ema_cs, out);
}

// round 14
// speedup vs baseline: 1.9193x; 1.9193x over previous
#include <cuda_runtime.h>
#include <cstdint>
#include <cstddef>

// Problem constants
#define NN 32768
#define KK 8192
#define DD 64

// Output layout (tuple order, flattened)
#define OFF_CB  268435456ULL
#define OFF_CS  268959744ULL
#define OFF_EMA 268967936ULL
#define OFF_EMB 269492224ULL

#define DECAY 0.99f
#define OMD   0.01f
#define EPSV  1e-5f
#define KEPS  0.08192f   // K * EPS

// Scratch (device globals; no allocations allowed)
__device__ int   g_idx[NN];
__device__ float g_e2[KK];
__device__ int   g_e2max_i;      // max ||e||^2 as ordered int (positive floats)
__device__ float g_cnt[KK];
__device__ float g_dw[KK * DD];
__device__ float g_n;

// ===========================================================================
// helpers (sm_80-era PTX only: safe for the plain sm_103 ptxas target)
// ===========================================================================
static __device__ __forceinline__ uint32_t smem_u32(const void* p) {
    uint32_t a;
    asm("{ .reg .u64 t; cvta.to.shared.u64 t, %1; cvt.u32.u64 %0, t; }"
        : "=r"(a) : "l"(p));
    return a;
}

#define CP_ASYNC16(dst, src) \
    asm volatile("cp.async.cg.shared.global [%0], [%1], 16;" \
                 :: "r"(dst), "l"(src) : "memory")
#define CP_COMMIT() asm volatile("cp.async.commit_group;" ::: "memory")
#define CP_WAIT0()  asm volatile("cp.async.wait_group 0;"  ::: "memory")

// m16n8k16 row.col bf16 MMA, D += A*B (C aliases D)
static __device__ __forceinline__ void mma_bf16(float* d, const uint32_t* a,
                                                const uint32_t* b) {
    asm volatile(
        "mma.sync.aligned.m16n8k16.row.col.f32.bf16.bf16.f32 "
        "{%0,%1,%2,%3}, {%4,%5,%6,%7}, {%8,%9}, {%0,%1,%2,%3};"
        : "+f"(d[0]), "+f"(d[1]), "+f"(d[2]), "+f"(d[3])
        : "r"(a[0]), "r"(a[1]), "r"(a[2]), "r"(a[3]), "r"(b[0]), "r"(b[1]));
}

// pack two f32 -> bf16x2 (lo = first element / even k, hi = odd k)
static __device__ __forceinline__ uint32_t pack_bf16(float lo, float hi) {
    uint32_t d;
    asm("cvt.rn.bf16x2.f32 %0, %1, %2;" : "=r"(d) : "f"(hi), "f"(lo));
    return d;
}

// ===========================================================================
// 0) zero scratch
// ===========================================================================
__global__ void zero_scratch_kernel() {
    int i = blockIdx.x * 256 + threadIdx.x;
    if (i < KK * DD) g_dw[i] = 0.0f;
    if (i < KK)      g_cnt[i] = 0.0f;
    if (i == 0)      g_e2max_i = 0;
}

// ===========================================================================
// 1) codebook squared norms + max norm
// ===========================================================================
__global__ void e2_kernel(const float* __restrict__ e) {
    int k = blockIdx.x * 256 + threadIdx.x;
    const float4* p = reinterpret_cast<const float4*>(e + (size_t)k * DD);
    float s = 0.0f;
#pragma unroll
    for (int i = 0; i < 16; ++i) {
        float4 v = p[i];
        s += v.x * v.x + v.y * v.y + v.z * v.z + v.w * v.w;
    }
    g_e2[k] = s;
    atomicMax(&g_e2max_i, __float_as_int(s));   // positive floats: int order ok
}

// ===========================================================================
// 2) Fused argmin (bf16 filter + ballot-cooperative exact rescue)
//    + encodings + scatter.
//    CTA = 256 threads = 8 warps, 4(m) x 2(n); 128 rows per CTA, 2 CTAs/SM
//    -> 256 CTAs = ONE full wave.
//    Approx distances via single-term bf16 m16n8k16 HMMA (A persistent, 32
//    regs).  Candidates within the provable 2-eps margin of the running
//    approx minimum are rescored exactly: the WHOLE warp computes the fp32
//    dot cooperatively (2 floats/lane + shfl tree), so rescues cost ~15 cyc
//    instead of a 640-cyc divergent serial dot.  Selection uses exact values
//    only.  One-hot zero stripe streams in the tile loop; 1.0-writes and
//    dw/count scatter in the tail.
// ===========================================================================
#define RPC  128
#define SP   68                       // smem row stride in floats (64 + 4 pad)
#define SPB  (SP * 4)                 // 272 bytes
#define PLANE (128 * SPB)             // 34816 bytes
#define XRAW 0
#define EB0  PLANE
#define EB1  (2 * PLANE)
#define XS2  (3 * PLANE)                  // [128] float row norms^2
#define CAND_D (XS2 + 128 * 4)            // [2][128] float
#define CAND_I (CAND_D + 2 * 128 * 4)     // [2][128] int
#define WIN_OFF (CAND_I + 2 * 128 * 4)    // [128] int
#define ARG_SMEM (WIN_OFF + 128 * 4)      // 107520 bytes

// margin = 2*eps, eps = 2*2.004*2^-8 * ||x|| * ||e||max, padded 1.34x
#define MARG_C 0.042f

__global__ __launch_bounds__(256, 2)
void argmin_mma_kernel(const float* __restrict__ x, const float* __restrict__ e,
                       float* __restrict__ out) {
    extern __shared__ char sm[];
    const uint32_t sb = smem_u32(sm);
    const int tid = threadIdx.x;
    const int wid = tid >> 5;
    const int lane = tid & 31;
    const int g = lane >> 2;          // group id (0..7)
    const int r = lane & 3;           // thread-in-group (0..3)
    const int mw = wid & 3;           // m-warp -> rows mw*32..+31
    const int nw = wid >> 2;          // n-warp -> cols nw*64..+63
    const int row0 = blockIdx.x * RPC;
    const int Cn = nw * 64;

    float* xs2    = reinterpret_cast<float*>(sm + XS2);
    float* cand_d = reinterpret_cast<float*>(sm + CAND_D);
    int*   cand_i = reinterpret_cast<int*>(sm + CAND_I);
    int*   win    = reinterpret_cast<int*>(sm + WIN_OFF);

    // ---- kick off e tile 0 prefetch (overlaps x staging) ----
    {
        const char* src = reinterpret_cast<const char*>(e);
#pragma unroll
        for (int i = 0; i < 8; ++i) {
            int ch = tid + 256 * i;
            int n = ch >> 4, kq = ch & 15;
            CP_ASYNC16(sb + EB0 + n * SPB + kq * 16, src + ch * 16);
        }
    }
    CP_COMMIT();

    // ---- stage raw x tile ----
    {
        const float4* xg = reinterpret_cast<const float4*>(x + (size_t)row0 * DD);
#pragma unroll
        for (int i = 0; i < 8; ++i) {
            int ch = tid + 256 * i;            // 0..2047 float4s
            int row = ch >> 4, q = ch & 15;
            *reinterpret_cast<float4*>(sm + XRAW + row * SPB + q * 16) = xg[ch];
        }
    }
    __syncthreads();

    // ---- row norms^2 ----
    if (tid < 128) {
        const float4* xr = reinterpret_cast<const float4*>(sm + XRAW + tid * SPB);
        float s = 0.0f;
#pragma unroll
        for (int i = 0; i < 16; ++i) {
            float4 v = xr[i];
            s += v.x * v.x + v.y * v.y + v.z * v.z + v.w * v.w;
        }
        xs2[tid] = s;
    }

    // ---- persistent bf16 A fragments: [mf][ks][4] ----
    uint32_t A[2][4][4];
#pragma unroll
    for (int mf = 0; mf < 2; ++mf)
#pragma unroll
        for (int ks = 0; ks < 4; ++ks)
#pragma unroll
            for (int j = 0; j < 4; ++j) {
                int row = mw * 32 + mf * 16 + g + ((j & 1) ? 8 : 0);
                int kb  = ks * 16 + ((j & 2) ? 8 : 0) + 2 * r;
                float2 v = *reinterpret_cast<const float2*>(
                    sm + XRAW + row * SPB + kb * 4);
                A[mf][ks][j] = pack_bf16(v.x, v.y);
            }

    CP_WAIT0();
    __syncthreads();

    // ---- per-slot state: rows mw*32 + g + s*8 ----
    const float emaxs = sqrtf(__int_as_float(g_e2max_i));
    float marg[4], cb[4], bex[4];
    int   bix[4];
#pragma unroll
    for (int s = 0; s < 4; ++s) {
        marg[s] = MARG_C * sqrtf(xs2[mw * 32 + g + s * 8]) * emaxs;
        cb[s]  = 3.402823466e38f;
        bex[s] = 3.402823466e38f;
        bix[s] = 0;
    }

    // encodings base (float4 granularity; row stride 2048 f4)
    float4* enc = reinterpret_cast<float4*>(out) + (size_t)row0 * 2048;
    const float4 fz = make_float4(0.0f, 0.0f, 0.0f, 0.0f);

    const int NTILES = KK / 128;   // 64
    for (int t = 0; t < NTILES; ++t) {
        const char* bufc = sm + (((t & 1) == 0) ? EB0 : EB1);

        // prefetch tile t+1
        if (t + 1 < NTILES) {
            const char* src = reinterpret_cast<const char*>(e + (size_t)(t + 1) * 128 * DD);
            const uint32_t bufn = sb + (((t & 1) == 0) ? EB1 : EB0);
#pragma unroll
            for (int i = 0; i < 8; ++i) {
                int ch = tid + 256 * i;
                int n = ch >> 4, kq = ch & 15;
                CP_ASYNC16(bufn + n * SPB + kq * 16, src + ch * 16);
            }
        }
        CP_COMMIT();

        // ---- zero stripe: rows [0,128) x f4-cols [t*32, t*32+32) ----
        {
            float4* zb = enc + t * 32;
#pragma unroll
            for (int j = 0; j < 16; ++j) {
                int i = tid + 256 * j;         // 0..4095
                int row = i >> 5, c4 = i & 31;
                __stcs(&zb[(size_t)row * 2048 + c4], fz);
            }
        }

        // ballot-cooperative rescue: flag cheap, exact dot warp-wide.
        auto process = [&](int s, int rowl, int colg, float e2v, float dacc) {
            float dt = fmaf(-2.0f, dacc, e2v);
            bool need = dt <= cb[s] + marg[s];
            cb[s] = fminf(cb[s], dt);
            unsigned msk = __ballot_sync(0xffffffffu, need);
            while (msk) {
                int src = __ffs(msk) - 1; msk &= msk - 1;
                int crow = __shfl_sync(0xffffffffu, rowl, src);
                int ccol = __shfl_sync(0xffffffffu, colg, src);
                float ce2 = __shfl_sync(0xffffffffu, e2v, src);
                const float2* xr = reinterpret_cast<const float2*>(
                    sm + XRAW + crow * SPB);
                const float2* er = reinterpret_cast<const float2*>(
                    bufc + (size_t)(ccol & 127) * SPB);
                float2 xv = xr[lane], ev = er[lane];
                float p = fmaf(xv.x, ev.x, xv.y * ev.y);
                p += __shfl_xor_sync(0xffffffffu, p, 16);
                p += __shfl_xor_sync(0xffffffffu, p, 8);
                p += __shfl_xor_sync(0xffffffffu, p, 4);
                p += __shfl_xor_sync(0xffffffffu, p, 2);
                p += __shfl_xor_sync(0xffffffffu, p, 1);
                float ex = fmaf(-2.0f, p, ce2);
                if (lane == src && ex < bex[s]) { bex[s] = ex; bix[s] = ccol; }
            }
        };

        // ---- compute in two n-halves (keeps regs under the 2-CTA budget) ----
#pragma unroll
        for (int h = 0; h < 2; ++h) {
            float D[2][4][4];
#pragma unroll
            for (int mf = 0; mf < 2; ++mf)
#pragma unroll
                for (int nb = 0; nb < 4; ++nb)
#pragma unroll
                    for (int j = 0; j < 4; ++j) D[mf][nb][j] = 0.0f;

#pragma unroll
            for (int ks = 0; ks < 4; ++ks) {
                uint32_t B[4][2];
#pragma unroll
                for (int nb = 0; nb < 4; ++nb) {
                    const char* np = bufc +
                        (size_t)(Cn + h * 32 + nb * 8 + g) * SPB;
                    float2 p0 = *reinterpret_cast<const float2*>(
                        np + (ks * 16 + 2 * r) * 4);
                    float2 p1 = *reinterpret_cast<const float2*>(
                        np + (ks * 16 + 2 * r + 8) * 4);
                    B[nb][0] = pack_bf16(p0.x, p0.y);
                    B[nb][1] = pack_bf16(p1.x, p1.y);
                }
#pragma unroll
                for (int nb = 0; nb < 4; ++nb) {
                    mma_bf16(D[0][nb], A[0][ks], B[nb]);
                    mma_bf16(D[1][nb], A[1][ks], B[nb]);
                }
            }

            // epilogue for this half
#pragma unroll
            for (int nb = 0; nb < 4; ++nb) {
                int col = t * 128 + Cn + h * 32 + nb * 8 + r * 2;
                float2 q = *reinterpret_cast<const float2*>(&g_e2[col]);
#pragma unroll
                for (int mf = 0; mf < 2; ++mf) {
                    int rowl = mw * 32 + mf * 16 + g;
                    int s0 = mf * 2, s1 = mf * 2 + 1;
                    process(s0, rowl,     col,     q.x, D[mf][nb][0]);
                    process(s0, rowl,     col + 1, q.y, D[mf][nb][1]);
                    process(s1, rowl + 8, col,     q.x, D[mf][nb][2]);
                    process(s1, rowl + 8, col + 1, q.y, D[mf][nb][3]);
                }
            }
        }

        CP_WAIT0();
        __syncthreads();
    }

    // ---- reduce exact results across the 4 lanes of each quad ----
#pragma unroll
    for (int m = 1; m <= 2; m <<= 1) {
#pragma unroll
        for (int s = 0; s < 4; ++s) {
            float ob = __shfl_xor_sync(0xffffffffu, bex[s], m);
            int   oi = __shfl_xor_sync(0xffffffffu, bix[s], m);
            if (ob < bex[s] || (ob == bex[s] && oi < bix[s])) {
                bex[s] = ob; bix[s] = oi;
            }
        }
    }
    if (r == 0) {
#pragma unroll
        for (int s = 0; s < 4; ++s) {
            int row = mw * 32 + g + s * 8;
            cand_d[nw * 128 + row] = bex[s];
            cand_i[nw * 128 + row] = bix[s];
        }
    }
    __syncthreads();   // also orders zero stores before the 1.0 stores
    if (tid < 128) {
        float d0 = cand_d[tid], d1 = cand_d[128 + tid];
        int   i0 = cand_i[tid], i1 = cand_i[128 + tid];
        int bi = (d1 < d0 || (d1 == d0 && i1 < i0)) ? i1 : i0;
        win[tid] = bi;
        g_idx[row0 + tid] = bi;
        out[(size_t)(row0 + tid) * KK + bi] = 1.0f;   // the one-hot 1
    }
    __syncthreads();

    // ---- fused dw/count scatter for this CTA's 128 rows (x from smem) ----
    for (int i = tid; i < RPC * DD; i += 256) {
        int n = i >> 6, d = i & 63;
        int k = win[n];
        float xv = *reinterpret_cast<const float*>(sm + XRAW + n * SPB + d * 4);
        atomicAdd(&g_dw[(size_t)k * DD + d], xv);
        if (d == 0) atomicAdd(&g_cnt[k], 1.0f);
    }
}

// ===========================================================================
// 3) n = sum(cluster_size_pre)
// ===========================================================================
__global__ void reduce_n_kernel(const float* __restrict__ ema_cs) {
    __shared__ float sh[1024];
    int t = threadIdx.x;
    float s = 0.0f;
    for (int k = t; k < KK; k += 1024) {
        float cs = __fadd_rn(__fmul_rn(ema_cs[k], DECAY), __fmul_rn(OMD, g_cnt[k]));
        s += cs;
    }
    sh[t] = s;
    __syncthreads();
    for (int m = 512; m > 0; m >>= 1) {
        if (t < m) sh[t] += sh[t + m];
        __syncthreads();
    }
    if (t == 0) g_n = sh[0];
}

// ===========================================================================
// 4) finalize
// ===========================================================================
__global__ void finalize_kernel(const float* __restrict__ emb_w,
                                const float* __restrict__ ema_w,
                                const float* __restrict__ ema_cs,
                                float* __restrict__ out) {
    int gid = blockIdx.x * 256 + threadIdx.x;
    int k = gid >> 6, d = gid & 63;
    float nsum = g_n;
    float cs  = __fadd_rn(__fmul_rn(ema_cs[k], DECAY), __fmul_rn(OMD, g_cnt[k]));
    float csn = __fmul_rn(__fdiv_rn(__fadd_rn(cs, EPSV), __fadd_rn(nsum, KEPS)), nsum);
    float ema_new = __fadd_rn(__fmul_rn(ema_w[gid], DECAY), __fmul_rn(OMD, g_dw[gid]));
    out[OFF_CB  + gid] = emb_w[gid];
    out[OFF_EMA + gid] = ema_new;
    out[OFF_EMB + gid] = __fdiv_rn(ema_new, csn);
    if (d == 0) out[OFF_CS + k] = csn;
}

// ===========================================================================
extern "C" void kernel_launch(void* const* d_in, const int* in_sizes, int n_in,
                              void* d_out, int out_size) {
    const float* x       = (const float*)d_in[0];
    const float* emb_w   = (const float*)d_in[1];
    const float* ema_w   = (const float*)d_in[2];
    const float* ema_cs  = (const float*)d_in[3];
    float* out = (float*)d_out;

    cudaFuncSetAttribute(argmin_mma_kernel,
                         cudaFuncAttributeMaxDynamicSharedMemorySize, ARG_SMEM);

    zero_scratch_kernel<<<2048, 256>>>();
    e2_kernel<<<KK / 256, 256>>>(emb_w);
    argmin_mma_kernel<<<NN / RPC, 256, ARG_SMEM>>>(x, emb_w, out);
    reduce_n_kernel<<<1, 1024>>>(ema_cs);
    finalize_kernel<<<(KK * DD) / 256, 256>>>(emb_w, ema_w, ema_cs, out);
}